// round 4
// baseline (speedup 1.0000x reference)
#include <cuda_runtime.h>
#include <math.h>

// Problem sizes (fixed by the reference)
#define TT 512
#define BB 128
#define HH 512
#define H3 1536

// ---------------- scratch (static __device__, no allocs) ----------------
__device__ float g_GI[TT * BB * H3];   // 402 MB: precomputed x@Wi + bi
__device__ float g_H[2 * BB * HH];     // double-buffered hidden state
__device__ float g_RS[TT * BB];        // reset multipliers: 0.0 = reset, 1.0 = keep
__device__ int   g_reset_mode;         // 0=int32, 1=byte, 2=float32
__device__ unsigned int g_count;       // grid barrier arrive counter
__device__ unsigned int g_gen;         // grid barrier generation

// ---------------- detect how the harness stored the bool resets ----------
// Scans the first T*B bytes (safe under any elem size >= 1B) and classifies
// by which byte positions (mod 4) ever hold nonzero data:
//   byte-bools  -> nonzeros at position 1 (and others)
//   int32 {0,1} -> nonzeros only at position 0
//   f32 {0,1}   -> nonzeros only at positions 2/3 (0x3F800000)
__global__ void detect_reset_mode_kernel(const unsigned char* __restrict__ r) {
    __shared__ int cnt[4];
    if (threadIdx.x < 4) cnt[threadIdx.x] = 0;
    __syncthreads();
    int local[4] = {0, 0, 0, 0};
    const uchar4* r4 = (const uchar4*)r;
    for (int i = threadIdx.x; i < (TT * BB) / 4; i += blockDim.x) {
        uchar4 v = r4[i];
        local[0] += (v.x != 0); local[1] += (v.y != 0);
        local[2] += (v.z != 0); local[3] += (v.w != 0);
    }
#pragma unroll
    for (int q = 0; q < 4; ++q) atomicAdd(&cnt[q], local[q]);
    __syncthreads();
    if (threadIdx.x == 0) {
        int mode;
        if (cnt[1] > 0) mode = 1;                       // dense byte bools
        else if (cnt[0] > 0) mode = 0;                  // little-endian int32 0/1
        else if (cnt[2] > 0 || cnt[3] > 0) mode = 2;    // float32 0.0/1.0
        else mode = 0;                                  // all-false: any mode ok
        g_reset_mode = mode;
    }
}

// ---------------- expand resets into fp32 keep-multipliers ----------------
__global__ void expand_resets_kernel(const void* __restrict__ resets) {
    int i = blockIdx.x * blockDim.x + threadIdx.x;
    if (i >= TT * BB) return;
    const int mode = g_reset_mode;
    bool rst;
    if (mode == 0)      rst = ((const int*)resets)[i] != 0;
    else if (mode == 1) rst = ((const unsigned char*)resets)[i] != 0;
    else                rst = ((const float*)resets)[i] != 0.0f;
    g_RS[i] = rst ? 0.0f : 1.0f;
}

// ---------------- init: reset barrier, load h0 ----------------
__global__ void init_kernel(const float* __restrict__ h0) {
    int i = blockIdx.x * blockDim.x + threadIdx.x;
    if (i == 0) { g_count = 0u; g_gen = 0u; }
    if (i < BB * HH) g_H[i] = h0[i];
}

// ---------------- GI GEMM: [65536,512] @ [512,1536] + bias ----------------
#define GM 128
#define GN 128
#define GK 16

__global__ __launch_bounds__(256) void gi_gemm_kernel(
    const float* __restrict__ A,     // x as [T*B, H]
    const float* __restrict__ Bm,    // Wi [H, 3H]
    const float* __restrict__ bias)  // bi [3H]
{
    __shared__ float As[GK][GM];        // transposed A tile
    __shared__ float Bs[GK][GN + 4];    // padded B tile

    const int n0 = blockIdx.x * GN;
    const int m0 = blockIdx.y * GM;
    const int tid = threadIdx.x;
    const int tx = tid & 15;   // n direction
    const int ty = tid >> 4;   // m direction

    float acc[8][8];
#pragma unroll
    for (int i = 0; i < 8; ++i)
#pragma unroll
        for (int j = 0; j < 8; ++j) acc[i][j] = 0.f;

    for (int k0 = 0; k0 < HH; k0 += GK) {
        // load A tile (128 rows x 16 k) as float4, store transposed
#pragma unroll
        for (int i = 0; i < 2; ++i) {
            int id = tid * 2 + i;            // 0..511
            int row = id >> 2;
            int c4 = id & 3;
            float4 v = *(const float4*)(A + (size_t)(m0 + row) * HH + k0 + c4 * 4);
            As[c4 * 4 + 0][row] = v.x;
            As[c4 * 4 + 1][row] = v.y;
            As[c4 * 4 + 2][row] = v.z;
            As[c4 * 4 + 3][row] = v.w;
        }
        // load B tile (16 k x 128 n)
#pragma unroll
        for (int i = 0; i < 2; ++i) {
            int id = tid * 2 + i;            // 0..511
            int kr = id >> 5;                // 0..15
            int n4 = id & 31;
            float4 v = *(const float4*)(Bm + (size_t)(k0 + kr) * H3 + n0 + n4 * 4);
            *(float4*)&Bs[kr][n4 * 4] = v;
        }
        __syncthreads();

#pragma unroll
        for (int kk = 0; kk < GK; ++kk) {
            float a[8], b[8];
            *(float4*)&a[0] = *(const float4*)&As[kk][ty * 8];
            *(float4*)&a[4] = *(const float4*)&As[kk][ty * 8 + 4];
            *(float4*)&b[0] = *(const float4*)&Bs[kk][tx * 8];
            *(float4*)&b[4] = *(const float4*)&Bs[kk][tx * 8 + 4];
#pragma unroll
            for (int i = 0; i < 8; ++i)
#pragma unroll
                for (int j = 0; j < 8; ++j)
                    acc[i][j] = fmaf(a[i], b[j], acc[i][j]);
        }
        __syncthreads();
    }

    // epilogue: add bias, store
    float bb[8];
#pragma unroll
    for (int q = 0; q < 8; ++q) bb[q] = bias[n0 + tx * 8 + q];

#pragma unroll
    for (int i = 0; i < 8; ++i) {
        int m = m0 + ty * 8 + i;
        float* dst = g_GI + (size_t)m * H3 + n0 + tx * 8;
        float4 o0, o1;
        o0.x = acc[i][0] + bb[0]; o0.y = acc[i][1] + bb[1];
        o0.z = acc[i][2] + bb[2]; o0.w = acc[i][3] + bb[3];
        o1.x = acc[i][4] + bb[4]; o1.y = acc[i][5] + bb[5];
        o1.z = acc[i][6] + bb[6]; o1.w = acc[i][7] + bb[7];
        *(float4*)(dst + 0) = o0;
        *(float4*)(dst + 4) = o1;
    }
}

// ---------------- persistent scan kernel ----------------
#define NCTA 128
#define SCAN_THREADS 128
#define CHK 128
#define HPITCH 132   // 128 + 4 pad -> conflict-free strided float4 LDS

// shared layout (floats): sWh[12*512] | sH[128*HPITCH] | sRs[128]
#define SMEM_FLOATS (12 * 512 + BB * HPITCH + BB)
#define SMEM_BYTES (SMEM_FLOATS * 4)

__device__ __forceinline__ void grid_sync(unsigned int nctas, unsigned int& gen) {
    __syncthreads();
    if (threadIdx.x == 0) {
        __threadfence();
        unsigned int prev = atomicAdd(&g_count, 1u);
        if (prev == nctas - 1u) {
            atomicExch(&g_count, 0u);
            __threadfence();
            atomicAdd(&g_gen, 1u);
        } else {
            unsigned int cur;
            do {
                asm volatile("ld.acquire.gpu.u32 %0, [%1];"
                             : "=r"(cur) : "l"(&g_gen) : "memory");
            } while (cur == gen);
        }
    }
    gen++;
    __syncthreads();
}

extern __shared__ float s_dyn[];

__global__ __launch_bounds__(SCAN_THREADS, 1) void scan_kernel(
    const float* __restrict__ Wh,              // [H, 3H]
    const float* __restrict__ bhn,             // [H]
    float* __restrict__ out)                   // [T,B,H]
{
    float* sWh = s_dyn;                    // [12][512]
    float* sH  = s_dyn + 12 * 512;         // [128][HPITCH]
    float* sRs = sH + BB * HPITCH;         // [128] 0/1 keep-multipliers

    const int tid = threadIdx.x;
    const int lane = tid & 31;
    const int cg = tid >> 5;               // 0..3 -> which of this CTA's 4 columns
    const int j = blockIdx.x * 4 + cg;     // output h-column handled by this thread

    // Load this CTA's 12 Wh gate-columns into SMEM once (resident all 512 steps)
    for (int p = tid; p < 12 * 512; p += SCAN_THREADS) {
        int idx = p >> 9;                  // 0..11
        int k = p & 511;
        int lcg = idx / 3;
        int g = idx - lcg * 3;
        int gcol = g * HH + blockIdx.x * 4 + lcg;
        sWh[p] = Wh[(size_t)k * H3 + gcol];
    }
    const float bhn_j = bhn[j];
    const int wb0 = (cg * 3 + 0) * 512;
    const int wb1 = (cg * 3 + 1) * 512;
    const int wb2 = (cg * 3 + 2) * 512;

    unsigned int gen = 0;

    for (int t = 0; t < TT; ++t) {
        const float* hsrc = g_H + (size_t)(t & 1) * BB * HH;
        float* hdst = g_H + (size_t)((t + 1) & 1) * BB * HH;

        // per-step keep-multipliers (precomputed fp32, layout-proof)
        sRs[tid] = g_RS[(size_t)t * BB + tid];
        __syncthreads();   // also covers sWh readiness at t==0

        float aR[4] = {0.f, 0.f, 0.f, 0.f};
        float aZ[4] = {0.f, 0.f, 0.f, 0.f};
        float aN[4] = {0.f, 0.f, 0.f, 0.f};

        for (int kc = 0; kc < HH; kc += CHK) {
            // stage h chunk [128 x 128] with reset applied
#pragma unroll
            for (int q = 0; q < (BB * CHK / 4) / SCAN_THREADS; ++q) {  // 32 iters
                int p = tid + q * SCAN_THREADS;   // 0..4095
                int b = p >> 5;
                int kq = p & 31;
                float4 v = *(const float4*)(hsrc + (size_t)b * HH + kc + kq * 4);
                float m = sRs[b];
                v.x *= m; v.y *= m; v.z *= m; v.w *= m;
                *(float4*)(sH + b * HPITCH + kq * 4) = v;
            }
            __syncthreads();

#pragma unroll 8
            for (int kk = 0; kk < CHK; kk += 4) {
                const int kg = kc + kk;
                const float4 wr = *(const float4*)(sWh + wb0 + kg);
                const float4 wz = *(const float4*)(sWh + wb1 + kg);
                const float4 wn = *(const float4*)(sWh + wb2 + kg);
#pragma unroll
                for (int ri = 0; ri < 4; ++ri) {
                    const float4 h4 = *(const float4*)(sH + (lane + 32 * ri) * HPITCH + kk);
                    aR[ri] = fmaf(h4.x, wr.x, fmaf(h4.y, wr.y, fmaf(h4.z, wr.z, fmaf(h4.w, wr.w, aR[ri]))));
                    aZ[ri] = fmaf(h4.x, wz.x, fmaf(h4.y, wz.y, fmaf(h4.z, wz.z, fmaf(h4.w, wz.w, aZ[ri]))));
                    aN[ri] = fmaf(h4.x, wn.x, fmaf(h4.y, wn.y, fmaf(h4.z, wn.z, fmaf(h4.w, wn.w, aN[ri]))));
                }
            }
            __syncthreads();
        }

        // gate combine + write new h and output
        const float* gi = g_GI + (size_t)t * BB * H3;
#pragma unroll
        for (int ri = 0; ri < 4; ++ri) {
            const int b = lane + 32 * ri;
            const float gir = gi[(size_t)b * H3 + j];
            const float giz = gi[(size_t)b * H3 + HH + j];
            const float gin = gi[(size_t)b * H3 + 2 * HH + j];
            const float hv = hsrc[(size_t)b * HH + j] * sRs[b];
            const float r = 1.f / (1.f + expf(-(aR[ri] + gir)));
            const float z = 1.f / (1.f + expf(-(aZ[ri] + giz)));
            const float n = tanhf(gin + r * (aN[ri] + bhn_j));
            const float nh = (1.f - z) * n + z * hv;
            hdst[(size_t)b * HH + j] = nh;
            out[((size_t)t * BB + b) * HH + j] = nh;
        }

        grid_sync(NCTA, gen);
    }
}

// ---------------- launch ----------------
extern "C" void kernel_launch(void* const* d_in, const int* in_sizes, int n_in,
                              void* d_out, int out_size) {
    const float* x    = (const float*)d_in[0];   // [T,B,H]
    const void*  rst  = d_in[1];                 // [T,B] bool (unknown storage)
    const float* Wi   = (const float*)d_in[2];   // [H,3H]
    const float* bi   = (const float*)d_in[3];   // [3H]
    const float* Wh   = (const float*)d_in[4];   // [H,3H]
    const float* bhn  = (const float*)d_in[5];   // [H]
    const float* h0   = (const float*)d_in[6];   // [B,H]
    float* out = (float*)d_out;

    (void)in_sizes; (void)n_in; (void)out_size;

    // classify resets storage layout, then expand to fp32 keep-multipliers
    detect_reset_mode_kernel<<<1, 256>>>((const unsigned char*)rst);
    expand_resets_kernel<<<(TT * BB + 255) / 256, 256>>>(rst);

    // reset barrier state + load h0 (graph-capturable, no allocs)
    init_kernel<<<(BB * HH + 255) / 256, 256>>>(h0);

    // GI = x @ Wi + bi over all timesteps at once
    dim3 ggrid(H3 / GN, (TT * BB) / GM);   // (12, 512)
    gi_gemm_kernel<<<ggrid, 256>>>(x, Wi, bi);

    // persistent sequential scan
    cudaFuncSetAttribute(scan_kernel,
                         cudaFuncAttributeMaxDynamicSharedMemorySize, SMEM_BYTES);
    scan_kernel<<<NCTA, SCAN_THREADS, SMEM_BYTES>>>(Wh, bhn, out);
}

// round 5
// speedup vs baseline: 1.7400x; 1.7400x over previous
#include <cuda_runtime.h>
#include <math.h>

// Problem sizes (fixed by the reference)
#define TT 512
#define BB 128
#define HH 512
#define H3 1536

// ---------------- scratch (static __device__, no allocs) ----------------
__device__ float g_GI[TT * BB * H3];       // precomputed x@Wi + bi
__device__ float g_Ht[2 * HH * BB];        // TRANSPOSED hidden state [buf][j][b], reset pre-applied
__device__ float g_RS[(TT + 1) * BB];      // keep multipliers: 0 = reset, 1 = keep (row TT = 1)
__device__ int   g_reset_mode;             // 0=int32, 1=byte, 2=float32
__device__ unsigned int g_count;           // grid barrier arrive counter
__device__ unsigned int g_gen;             // grid barrier generation

// ---------------- f32x2 packed-FMA helpers (FFMA2) ----------------
__device__ __forceinline__ unsigned long long pack2(float lo, float hi) {
    unsigned long long r;
    asm("mov.b64 %0, {%1, %2};" : "=l"(r) : "f"(lo), "f"(hi));
    return r;
}
__device__ __forceinline__ float2 unpack2(unsigned long long v) {
    float2 f;
    asm("mov.b64 {%0, %1}, %2;" : "=f"(f.x), "=f"(f.y) : "l"(v));
    return f;
}
__device__ __forceinline__ void fma2(unsigned long long& d,
                                     unsigned long long a, unsigned long long b) {
    asm("fma.rn.f32x2 %0, %1, %2, %0;" : "+l"(d) : "l"(a), "l"(b));
}
// 16B async copy gmem -> smem (L1 bypass)
__device__ __forceinline__ void cp16(void* dst, const void* src) {
    unsigned s = (unsigned)__cvta_generic_to_shared(dst);
    asm volatile("cp.async.cg.shared.global [%0], [%1], 16;" :: "r"(s), "l"(src));
}

// ---------------- detect how the harness stored the bool resets ----------
__global__ void detect_reset_mode_kernel(const unsigned char* __restrict__ r) {
    __shared__ int cnt[4];
    if (threadIdx.x < 4) cnt[threadIdx.x] = 0;
    __syncthreads();
    int local[4] = {0, 0, 0, 0};
    const uchar4* r4 = (const uchar4*)r;
    for (int i = threadIdx.x; i < (TT * BB) / 4; i += blockDim.x) {
        uchar4 v = r4[i];
        local[0] += (v.x != 0); local[1] += (v.y != 0);
        local[2] += (v.z != 0); local[3] += (v.w != 0);
    }
#pragma unroll
    for (int q = 0; q < 4; ++q) atomicAdd(&cnt[q], local[q]);
    __syncthreads();
    if (threadIdx.x == 0) {
        int mode;
        if (cnt[1] > 0) mode = 1;                       // dense byte bools
        else if (cnt[0] > 0) mode = 0;                  // little-endian int32 0/1
        else if (cnt[2] > 0 || cnt[3] > 0) mode = 2;    // float32 0.0/1.0
        else mode = 0;
        g_reset_mode = mode;
    }
}

// ---------------- expand resets into fp32 keep-multipliers ----------------
__global__ void expand_resets_kernel(const void* __restrict__ resets) {
    int i = blockIdx.x * blockDim.x + threadIdx.x;
    if (i >= (TT + 1) * BB) return;
    if (i >= TT * BB) { g_RS[i] = 1.0f; return; }
    const int mode = g_reset_mode;
    bool rst;
    if (mode == 0)      rst = ((const int*)resets)[i] != 0;
    else if (mode == 1) rst = ((const unsigned char*)resets)[i] != 0;
    else                rst = ((const float*)resets)[i] != 0.0f;
    g_RS[i] = rst ? 0.0f : 1.0f;
}

// ---------------- init: reset barrier, load transposed h0 with keep(0) ----
__global__ void init_kernel(const float* __restrict__ h0) {
    int i = blockIdx.x * blockDim.x + threadIdx.x;
    if (i == 0) { g_count = 0u; g_gen = 0u; }
    if (i < BB * HH) {
        int b = i >> 9;          // / HH
        int j = i & (HH - 1);
        g_Ht[j * BB + b] = h0[i] * g_RS[b];
    }
}

// ---------------- GI GEMM: [65536,512] @ [512,1536] + bias (FFMA2) --------
#define GM 128
#define GN 128
#define GK 16

__global__ __launch_bounds__(256) void gi_gemm_kernel(
    const float* __restrict__ A,     // x as [T*B, H]
    const float* __restrict__ Bm,    // Wi [H, 3H]
    const float* __restrict__ bias)  // bi [3H]
{
    __shared__ float As[GK][GM];        // transposed A tile
    __shared__ float Bs[GK][GN + 4];    // padded B tile

    const int n0 = blockIdx.x * GN;
    const int m0 = blockIdx.y * GM;
    const int tid = threadIdx.x;
    const int tx = tid & 15;   // n direction
    const int ty = tid >> 4;   // m direction

    // acc pairs along n: acc2[i][jp] holds columns (2jp, 2jp+1)
    unsigned long long acc2[8][4];
#pragma unroll
    for (int i = 0; i < 8; ++i)
#pragma unroll
        for (int jp = 0; jp < 4; ++jp) acc2[i][jp] = 0ull;

    for (int k0 = 0; k0 < HH; k0 += GK) {
        // load A tile (128 rows x 16 k) as float4, store transposed
#pragma unroll
        for (int i = 0; i < 2; ++i) {
            int id = tid * 2 + i;            // 0..511
            int row = id >> 2;
            int c4 = id & 3;
            float4 v = *(const float4*)(A + (size_t)(m0 + row) * HH + k0 + c4 * 4);
            As[c4 * 4 + 0][row] = v.x;
            As[c4 * 4 + 1][row] = v.y;
            As[c4 * 4 + 2][row] = v.z;
            As[c4 * 4 + 3][row] = v.w;
        }
        // load B tile (16 k x 128 n)
#pragma unroll
        for (int i = 0; i < 2; ++i) {
            int id = tid * 2 + i;            // 0..511
            int kr = id >> 5;                // 0..15
            int n4 = id & 31;
            float4 v = *(const float4*)(Bm + (size_t)(k0 + kr) * H3 + n0 + n4 * 4);
            *(float4*)&Bs[kr][n4 * 4] = v;
        }
        __syncthreads();

#pragma unroll 8
        for (int kk = 0; kk < GK; ++kk) {
            float a[8];
            *(float4*)&a[0] = *(const float4*)&As[kk][ty * 8];
            *(float4*)&a[4] = *(const float4*)&As[kk][ty * 8 + 4];
            const ulonglong2 b01 = *(const ulonglong2*)&Bs[kk][tx * 8];
            const ulonglong2 b23 = *(const ulonglong2*)&Bs[kk][tx * 8 + 4];
#pragma unroll
            for (int i = 0; i < 8; ++i) {
                unsigned long long ai = pack2(a[i], a[i]);
                fma2(acc2[i][0], ai, b01.x);
                fma2(acc2[i][1], ai, b01.y);
                fma2(acc2[i][2], ai, b23.x);
                fma2(acc2[i][3], ai, b23.y);
            }
        }
        __syncthreads();
    }

    // epilogue: add bias, store
    float bb[8];
#pragma unroll
    for (int q = 0; q < 8; ++q) bb[q] = bias[n0 + tx * 8 + q];

#pragma unroll
    for (int i = 0; i < 8; ++i) {
        int m = m0 + ty * 8 + i;
        float* dst = g_GI + (size_t)m * H3 + n0 + tx * 8;
        float2 p0 = unpack2(acc2[i][0]);
        float2 p1 = unpack2(acc2[i][1]);
        float2 p2 = unpack2(acc2[i][2]);
        float2 p3 = unpack2(acc2[i][3]);
        float4 o0, o1;
        o0.x = p0.x + bb[0]; o0.y = p0.y + bb[1];
        o0.z = p1.x + bb[2]; o0.w = p1.y + bb[3];
        o1.x = p2.x + bb[4]; o1.y = p2.y + bb[5];
        o1.z = p3.x + bb[6]; o1.w = p3.y + bb[7];
        *(float4*)(dst + 0) = o0;
        *(float4*)(dst + 4) = o1;
    }
}

// ---------------- persistent scan kernel ----------------
#define NCTA 128
#define SCAN_THREADS 128

// smem layout (floats):
//   sWh  [512][12]          6144   (24KB) : this CTA's 12 gate-cols, [k][c], c = hcol*3+g
//   sHT  [2][128][128]     32768  (128KB) : double-buffered h^T chunks [k_local][b]
//   sGI  [3][128][4]        1536    (6KB) : staged gi slice for this step
//   sRed [4][32][52]        6656   (26KB) : per-warp partial sums (pad 52 vs 48)
#define SWH_OFF  0
#define SHT_OFF  6144
#define SGI_OFF  (6144 + 32768)
#define SRED_OFF (6144 + 32768 + 1536)
#define SCAN_SMEM_FLOATS (6144 + 32768 + 1536 + 6656)
#define SCAN_SMEM_BYTES (SCAN_SMEM_FLOATS * 4)

__device__ __forceinline__ void grid_sync(unsigned int nctas, unsigned int& gen) {
    __syncthreads();
    if (threadIdx.x == 0) {
        __threadfence();
        unsigned int prev = atomicAdd(&g_count, 1u);
        if (prev == nctas - 1u) {
            atomicExch(&g_count, 0u);
            __threadfence();
            atomicAdd(&g_gen, 1u);
        } else {
            unsigned int cur;
            do {
                asm volatile("ld.acquire.gpu.u32 %0, [%1];"
                             : "=r"(cur) : "l"(&g_gen) : "memory");
            } while (cur == gen);
        }
    }
    gen++;
    __syncthreads();
}

extern __shared__ float smf[];

__global__ __launch_bounds__(SCAN_THREADS, 1) void scan_kernel(
    const float* __restrict__ Wh,              // [H, 3H]
    const float* __restrict__ bhn,             // [H]
    float* __restrict__ out)                   // [T,B,H]
{
    float* sWh  = smf + SWH_OFF;
    float* sHT  = smf + SHT_OFF;
    float* sGI  = smf + SGI_OFF;
    float* sRed = smf + SRED_OFF;

    const int tid  = threadIdx.x;
    const int lane = tid & 31;
    const int wid  = tid >> 5;             // warp = k-slice owner AND epilogue col group
    const int jbase = blockIdx.x * 4;
    const int cj = jbase >> 7;             // chunk containing this CTA's h-columns
    const int cg = wid;
    const int j = jbase + cg;
    const float bhn_j = bhn[j];

    // load this CTA's 12 Wh gate-columns once: sWh[k*12 + c], c = hcol*3 + g
    for (int p = tid; p < 6144; p += SCAN_THREADS) {
        int k = p / 12, c = p % 12;
        sWh[p] = Wh[(size_t)k * H3 + (c % 3) * HH + jbase + c / 3];
    }
    __syncthreads();

    unsigned int gen = 0;

    for (int t = 0; t < TT; ++t) {
        const float* hsrc = g_Ht + (t & 1) * HH * BB;          // h^T, reset applied
        float* hdst       = g_Ht + ((t + 1) & 1) * HH * BB;
        const float* gi   = g_GI + (size_t)t * BB * H3;

        // stage chunk 0 (h^T rows 0..127) + gi slice  -> commit group
#pragma unroll
        for (int q = 0; q < 32; ++q) {
            int p = tid + q * SCAN_THREADS;
            int kr = p >> 5, c4 = p & 31;
            cp16(sHT + kr * 128 + c4 * 4, hsrc + (size_t)kr * BB + c4 * 4);
        }
#pragma unroll
        for (int g = 0; g < 3; ++g)
            cp16(sGI + (g * 128 + tid) * 4, gi + (size_t)tid * H3 + g * HH + jbase);
        asm volatile("cp.async.commit_group;");

        // per-warp k-slice accumulators: rows b = 4*lane + r, col-pairs (2p,2p+1)
        unsigned long long acc[4][6];
#pragma unroll
        for (int r = 0; r < 4; ++r)
#pragma unroll
            for (int p = 0; p < 6; ++p) acc[r][p] = 0ull;

        float hv[4];

        for (int c = 0; c < 4; ++c) {
            if (c < 3) {
                float* dstb = sHT + ((c + 1) & 1) * 16384;
#pragma unroll
                for (int q = 0; q < 32; ++q) {
                    int p = tid + q * SCAN_THREADS;
                    int kr = p >> 5, c4 = p & 31;
                    cp16(dstb + kr * 128 + c4 * 4,
                         hsrc + (size_t)((c + 1) * 128 + kr) * BB + c4 * 4);
                }
                asm volatile("cp.async.commit_group;");
                asm volatile("cp.async.wait_group 1;");
            } else {
                asm volatile("cp.async.wait_group 0;");
            }
            __syncthreads();

            const float* hb = sHT + (c & 1) * 16384;
            const float* hw = hb + (wid * 32) * 128;                 // warp's k rows
            const float* ww = sWh + (c * 128 + wid * 32) * 12;       // matching weights

#pragma unroll 4
            for (int kk = 0; kk < 32; ++kk) {
                const float4 h4 = *(const float4*)(hw + kk * 128 + lane * 4);
                const ulonglong2 wA = *(const ulonglong2*)(ww + kk * 12);
                const ulonglong2 wB = *(const ulonglong2*)(ww + kk * 12 + 4);
                const ulonglong2 wC = *(const ulonglong2*)(ww + kk * 12 + 8);
                unsigned long long hp;
                hp = pack2(h4.x, h4.x);
                fma2(acc[0][0], hp, wA.x); fma2(acc[0][1], hp, wA.y);
                fma2(acc[0][2], hp, wB.x); fma2(acc[0][3], hp, wB.y);
                fma2(acc[0][4], hp, wC.x); fma2(acc[0][5], hp, wC.y);
                hp = pack2(h4.y, h4.y);
                fma2(acc[1][0], hp, wA.x); fma2(acc[1][1], hp, wA.y);
                fma2(acc[1][2], hp, wB.x); fma2(acc[1][3], hp, wB.y);
                fma2(acc[1][4], hp, wC.x); fma2(acc[1][5], hp, wC.y);
                hp = pack2(h4.z, h4.z);
                fma2(acc[2][0], hp, wA.x); fma2(acc[2][1], hp, wA.y);
                fma2(acc[2][2], hp, wB.x); fma2(acc[2][3], hp, wB.y);
                fma2(acc[2][4], hp, wC.x); fma2(acc[2][5], hp, wC.y);
                hp = pack2(h4.w, h4.w);
                fma2(acc[3][0], hp, wA.x); fma2(acc[3][1], hp, wA.y);
                fma2(acc[3][2], hp, wB.x); fma2(acc[3][3], hp, wB.y);
                fma2(acc[3][4], hp, wC.x); fma2(acc[3][5], hp, wC.y);
            }

            // grab old-h values for the epilogue while their chunk is resident
            if (c == cj) {
#pragma unroll
                for (int ri = 0; ri < 4; ++ri)
                    hv[ri] = hb[((jbase & 127) + cg) * 128 + lane + 32 * ri];
            }
            __syncthreads();
        }

        // cross-warp reduction via smem
        {
            float vals[48];
#pragma unroll
            for (int r = 0; r < 4; ++r)
#pragma unroll
                for (int p = 0; p < 6; ++p) {
                    float2 f = unpack2(acc[r][p]);
                    vals[r * 12 + 2 * p]     = f.x;
                    vals[r * 12 + 2 * p + 1] = f.y;
                }
            float* dst = sRed + tid * 52;
#pragma unroll
            for (int q = 0; q < 12; ++q)
                *(float4*)(dst + q * 4) = *(const float4*)&vals[q * 4];
        }
        __syncthreads();

        // epilogue: thread handles (b = lane + 32*ri, column j = jbase + cg)
#pragma unroll
        for (int ri = 0; ri < 4; ++ri) {
            const int b = lane + 32 * ri;
            const int base = (b >> 2) * 52 + (b & 3) * 12 + cg * 3;
            float aR = 0.f, aZ = 0.f, aN = 0.f;
#pragma unroll
            for (int w = 0; w < 4; ++w) {
                const float* p = sRed + w * (32 * 52) + base;
                aR += p[0]; aZ += p[1]; aN += p[2];
            }
            const float gir = sGI[(0 * 128 + b) * 4 + cg];
            const float giz = sGI[(1 * 128 + b) * 4 + cg];
            const float gin = sGI[(2 * 128 + b) * 4 + cg];
            const float rr = 1.f / (1.f + expf(-(aR + gir)));
            const float zz = 1.f / (1.f + expf(-(aZ + giz)));
            const float nn = tanhf(gin + rr * (aN + bhn_j));
            const float nh = (1.f - zz) * nn + zz * hv[ri];
            out[((size_t)t * BB + b) * HH + j] = nh;
            // fold NEXT step's reset into the stored state (transposed, coalesced)
            hdst[(size_t)j * BB + b] = nh * g_RS[(t + 1) * BB + b];
        }

        grid_sync(NCTA, gen);
    }
}

// ---------------- launch ----------------
extern "C" void kernel_launch(void* const* d_in, const int* in_sizes, int n_in,
                              void* d_out, int out_size) {
    const float* x    = (const float*)d_in[0];   // [T,B,H]
    const void*  rst  = d_in[1];                 // [T,B] bool (unknown storage)
    const float* Wi   = (const float*)d_in[2];   // [H,3H]
    const float* bi   = (const float*)d_in[3];   // [3H]
    const float* Wh   = (const float*)d_in[4];   // [H,3H]
    const float* bhn  = (const float*)d_in[5];   // [H]
    const float* h0   = (const float*)d_in[6];   // [B,H]
    float* out = (float*)d_out;

    (void)in_sizes; (void)n_in; (void)out_size;

    // classify resets storage layout, then expand to fp32 keep-multipliers
    detect_reset_mode_kernel<<<1, 256>>>((const unsigned char*)rst);
    expand_resets_kernel<<<((TT + 1) * BB + 255) / 256, 256>>>(rst);

    // reset barrier state + load transposed h0 with keep(0) applied
    init_kernel<<<(BB * HH + 255) / 256, 256>>>(h0);

    // GI = x @ Wi + bi over all timesteps at once
    dim3 ggrid(H3 / GN, (TT * BB) / GM);   // (12, 512)
    gi_gemm_kernel<<<ggrid, 256>>>(x, Wi, bi);

    // persistent sequential scan
    cudaFuncSetAttribute(scan_kernel,
                         cudaFuncAttributeMaxDynamicSharedMemorySize, SCAN_SMEM_BYTES);
    scan_kernel<<<NCTA, SCAN_THREADS, SCAN_SMEM_BYTES>>>(Wh, bhn, out);
}